// round 11
// baseline (speedup 1.0000x reference)
#include <cuda_runtime.h>

// out[t][l][d]: l==0 -> inputs[t][d], else memory[l][d]
// T=2048, L=64, D=1024 fp32. Pure store-bandwidth kernel (512 MiB writes).
//
// Spread-sweep endpoint: U=1 — one block per output row, oe*MLP_p1 = 8,
// below the B300 cross-CTA L1tex contention knee (spread floor ~1.10).
// Sweep history: U=8 -> 75.0us, U=4 -> 74.2us, U=2 -> 73.9us.
// Row index math is per-block (uniform), per-thread cost ~zero.
// .cs streaming stores (R8 A/B: beats write-back by 8us).

static constexpr int T = 2048;
static constexpr int L = 64;
static constexpr int D4 = 1024 / 4;            // 256 float4 per row
static constexpr int ROWS = T * L;             // 131072

__global__ __launch_bounds__(256, 8)
void sliding_window_memory_kernel(const float4* __restrict__ in,
                                  const float4* __restrict__ mem,
                                  float4* __restrict__ out)
{
    const int tid = threadIdx.x;
    const int row = blockIdx.x;
    const int l = row & (L - 1);
    const int t = row >> 6;

    const float4* __restrict__ s =
        (l == 0) ? (in + t * D4 + tid) : (mem + l * D4 + tid);

    __stcs(out + (long)row * D4 + tid, __ldg(s));
}

extern "C" void kernel_launch(void* const* d_in, const int* in_sizes, int n_in,
                              void* d_out, int out_size)
{
    const float4* in  = (const float4*)d_in[0];   // inputs [T, D] fp32
    const float4* mem = (const float4*)d_in[1];   // memory [L, D] fp32
    float4* out = (float4*)d_out;                 // [T, L, D] fp32

    sliding_window_memory_kernel<<<ROWS, 256>>>(in, mem, out);
}